// round 2
// baseline (speedup 1.0000x reference)
#include <cuda_runtime.h>
#include <cfloat>

#define S_LEN   2560
#define NVEC    (S_LEN / 4)      // 640 float4 per row
#define THREADS 256
#define NWARPS  (THREADS / 32)

// ---------------------------------------------------------------------------
// Batched block reductions. `scratch` must hold NWARPS * N floats.
// Results are broadcast to all threads (vals[] updated in place).
// ---------------------------------------------------------------------------
template <int N>
__device__ __forceinline__ void block_reduce_sum(float* vals, float* scratch) {
    #pragma unroll
    for (int o = 16; o > 0; o >>= 1)
        #pragma unroll
        for (int k = 0; k < N; ++k)
            vals[k] += __shfl_down_sync(0xffffffffu, vals[k], o);

    const int warp = threadIdx.x >> 5;
    const int lane = threadIdx.x & 31;
    if (lane == 0) {
        #pragma unroll
        for (int k = 0; k < N; ++k) scratch[warp * N + k] = vals[k];
    }
    __syncthreads();
    if (warp == 0) {
        #pragma unroll
        for (int k = 0; k < N; ++k) {
            float v = (lane < NWARPS) ? scratch[lane * N + k] : 0.0f;
            #pragma unroll
            for (int o = NWARPS / 2; o > 0; o >>= 1)
                v += __shfl_down_sync(0xffffffffu, v, o);
            if (lane == 0) scratch[k] = v;
        }
    }
    __syncthreads();
    #pragma unroll
    for (int k = 0; k < N; ++k) vals[k] = scratch[k];
    __syncthreads();  // protect scratch before any reuse
}

template <int N>
__device__ __forceinline__ void block_reduce_max(float* vals, float* scratch) {
    #pragma unroll
    for (int o = 16; o > 0; o >>= 1)
        #pragma unroll
        for (int k = 0; k < N; ++k)
            vals[k] = fmaxf(vals[k], __shfl_down_sync(0xffffffffu, vals[k], o));

    const int warp = threadIdx.x >> 5;
    const int lane = threadIdx.x & 31;
    if (lane == 0) {
        #pragma unroll
        for (int k = 0; k < N; ++k) scratch[warp * N + k] = vals[k];
    }
    __syncthreads();
    if (warp == 0) {
        #pragma unroll
        for (int k = 0; k < N; ++k) {
            float v = (lane < NWARPS) ? scratch[lane * N + k] : -FLT_MAX;
            #pragma unroll
            for (int o = NWARPS / 2; o > 0; o >>= 1)
                v = fmaxf(v, __shfl_down_sync(0xffffffffu, v, o));
            if (lane == 0) scratch[k] = v;
        }
    }
    __syncthreads();
    #pragma unroll
    for (int k = 0; k < N; ++k) vals[k] = scratch[k];
    __syncthreads();
}

__device__ __forceinline__ float sgnf(float x) {
    return (x > 0.0f) ? 1.0f : ((x < 0.0f) ? -1.0f : 0.0f);
}

// ---------------------------------------------------------------------------
// One CTA per row. Row staged in SMEM; one HBM read of the whole input.
// All passes vectorized over float4.
// ---------------------------------------------------------------------------
__global__ __launch_bounds__(THREADS)
void health_stats_kernel(const float* __restrict__ in,
                         float* __restrict__ out) {
    __shared__ float s[S_LEN];
    __shared__ float scratch[NWARPS * 8];

    const int b = blockIdx.x;
    const float4* row4 = reinterpret_cast<const float4*>(in + (size_t)b * S_LEN);
    float4* s4 = reinterpret_cast<float4*>(s);

    // Stage row into SMEM: 640 float4 loads, fully coalesced.
    for (int i = threadIdx.x; i < NVEC; i += THREADS)
        s4[i] = row4[i];
    __syncthreads();

    // ---------------- Pass 1: raw moments + extrema + zcr + Hjorth raw ------
    // acc: [0]=sum [1]=sumsq [2]=abssum [3]=zc [4]=sum_d1 [5]=sumsq_d1
    //      [6]=sum_d2 [7]=sumsq_d2
    float acc[8];
    #pragma unroll
    for (int k = 0; k < 8; ++k) acc[k] = 0.0f;
    float mx[3];  // [0]=max(x) [1]=max(-x) [2]=max(|x|)
    mx[0] = -FLT_MAX; mx[1] = -FLT_MAX; mx[2] = 0.0f;

    for (int i = threadIdx.x; i < NVEC; i += THREADS) {
        const float4 v = s4[i];
        const float e0 = v.x, e1 = v.y, e2 = v.z, e3 = v.w;

        // element-wise stats (4 at a time)
        acc[0] += (e0 + e1) + (e2 + e3);
        acc[1] += (e0 * e0 + e1 * e1) + (e2 * e2 + e3 * e3);
        acc[2] += (fabsf(e0) + fabsf(e1)) + (fabsf(e2) + fabsf(e3));
        mx[0] = fmaxf(fmaxf(mx[0], e0), fmaxf(fmaxf(e1, e2), e3));
        mx[1] = fmaxf(fmaxf(mx[1], -e0), fmaxf(fmaxf(-e1, -e2), -e3));
        mx[2] = fmaxf(fmaxf(mx[2], fabsf(e0)),
                      fmaxf(fmaxf(fabsf(e1), fabsf(e2)), fabsf(e3)));

        const bool tail = (i < NVEC - 1);
        float e4 = 0.0f, e5 = 0.0f;
        if (tail) {
            const float2 t = *reinterpret_cast<const float2*>(s + 4 * i + 4);
            e4 = t.x; e5 = t.y;
        }

        // first differences d1[p] = x[p+1]-x[p], p = 4i..4i+3 (last needs e4)
        const float d10 = e1 - e0;
        const float d11 = e2 - e1;
        const float d12 = e3 - e2;
        const float d13 = e4 - e3;            // only valid if tail

        // zero crossings over the same pairs
        const float sg0 = sgnf(e0), sg1 = sgnf(e1), sg2 = sgnf(e2),
                    sg3 = sgnf(e3), sg4 = sgnf(e4);
        float zc = ((sg0 != sg1) ? 1.0f : 0.0f)
                 + ((sg1 != sg2) ? 1.0f : 0.0f)
                 + ((sg2 != sg3) ? 1.0f : 0.0f);

        float sd1  = (d10 + d11) + d12;
        float sqd1 = (d10 * d10 + d11 * d11) + d12 * d12;

        // second differences d2[p] = d1[p+1]-d1[p], p = 4i..4i+3 (needs e4,e5)
        const float dd0 = d11 - d10;
        const float dd1 = d12 - d11;
        float sd2  = dd0 + dd1;
        float sqd2 = dd0 * dd0 + dd1 * dd1;

        if (tail) {
            zc   += (sg3 != sg4) ? 1.0f : 0.0f;
            sd1  += d13;
            sqd1 += d13 * d13;
            const float dd2 = d13 - d12;
            const float dd3 = (e5 - e4) - d13;
            sd2  += dd2 + dd3;
            sqd2 += dd2 * dd2 + dd3 * dd3;
        }

        acc[3] += zc;
        acc[4] += sd1;
        acc[5] += sqd1;
        acc[6] += sd2;
        acc[7] += sqd2;
    }
    block_reduce_sum<8>(acc, scratch);
    block_reduce_max<3>(mx, scratch);

    const float n      = (float)S_LEN;
    const float sum    = acc[0];
    const float sumsq  = acc[1];
    const float abssum = acc[2];
    const float zc     = acc[3];
    const float sd1    = acc[4], sqd1 = acc[5];
    const float sd2    = acc[6], sqd2 = acc[7];
    const float maximum = mx[0];
    const float minimum = -mx[1];
    const float absmax  = mx[2];

    const float mean = sum / n;

    // ---------------- Pass 2: centered moments (two-pass, accurate) --------
    float c[3];  // [0]=sum c^2, [1]=sum c^3, [2]=sum c^4
    c[0] = c[1] = c[2] = 0.0f;
    for (int i = threadIdx.x; i < NVEC; i += THREADS) {
        const float4 v = s4[i];
        const float c0 = v.x - mean, c1 = v.y - mean,
                    c2 = v.z - mean, c3 = v.w - mean;
        const float q0 = c0 * c0, q1 = c1 * c1, q2 = c2 * c2, q3 = c3 * c3;
        c[0] += (q0 + q1) + (q2 + q3);
        c[1] += (q0 * c0 + q1 * c1) + (q2 * c2 + q3 * c3);
        c[2] += (q0 * q0 + q1 * q1) + (q2 * q2 + q3 * q3);
    }
    block_reduce_sum<3>(c, scratch);

    const float var = c[0] / (n - 1.0f);     // unbiased
    const float std = sqrtf(var);

    // ---------------- Pass 3: outlier count with exact std -----------------
    float outl[1];
    outl[0] = 0.0f;
    const float thr = 3.0f * std;
    for (int i = threadIdx.x; i < NVEC; i += THREADS) {
        const float4 v = s4[i];
        outl[0] += ((fabsf(v.x - mean) > thr) ? 1.0f : 0.0f)
                 + ((fabsf(v.y - mean) > thr) ? 1.0f : 0.0f)
                 + ((fabsf(v.z - mean) > thr) ? 1.0f : 0.0f)
                 + ((fabsf(v.w - mean) > thr) ? 1.0f : 0.0f);
    }
    block_reduce_sum<1>(outl, scratch);

    // ---------------- Final scalars ----------------------------------------
    if (threadIdx.x == 0) {
        const float rms      = sqrtf(sumsq / n);
        const float skewness = (c[1] / n) / (std * std * std);
        const float kurtosis = (c[2] / n) / (var * var);
        const float shape    = rms * n / abssum;
        const float impulse  = absmax * n / abssum;
        const float zcr      = zc / (2.0f * n);

        const float n1 = n - 1.0f;              // #d1 elements = 2559
        const float n2 = n - 2.0f;              // #d2 elements = 2558
        const float var_d1 = (sqd1 - sd1 * sd1 / n1) / (n1 - 1.0f);
        const float var_d2 = (sqd2 - sd2 * sd2 / n2) / (n2 - 1.0f);
        const float mobility   = sqrtf(var_d1 / var);
        const float complexity = sqrtf(var_d2 / var_d1);

        float* o = out + (size_t)b * 15;
        o[0]  = mean;
        o[1]  = maximum;
        o[2]  = minimum;
        o[3]  = maximum - minimum;
        o[4]  = var;
        o[5]  = rms;
        o[6]  = skewness;
        o[7]  = kurtosis;
        o[8]  = shape;
        o[9]  = impulse;
        o[10] = outl[0];
        o[11] = zcr;
        o[12] = var;          // activity
        o[13] = mobility;
        o[14] = complexity;
    }
}

extern "C" void kernel_launch(void* const* d_in, const int* in_sizes, int n_in,
                              void* d_out, int out_size) {
    const float* in  = (const float*)d_in[0];
    float* out       = (float*)d_out;
    const int B = in_sizes[0] / S_LEN;   // 16384 rows of 2560 (x1)
    health_stats_kernel<<<B, THREADS>>>(in, out);
}